// round 1
// baseline (speedup 1.0000x reference)
#include <cuda_runtime.h>
#include <cstdint>

// Problem constants
#define HH   80
#define WW   120
#define TT   12
#define CIN  6
#define FF   32      // GRU filters per direction
#define NBATCH 2
#define CA   38      // fused input channels: x(6) + state(32)
#define FA   64      // kernel A outputs: z(32), r(32)
#define FB   32      // kernel B outputs: h-candidate
// Tiling
#define TY   14
#define TX   20
#define SH   (TY+2)  // 16
#define SWID (TX+2)  // 22
#define TILESX 6
#define TILESY 6     // 6*14 = 84 rows, covers 80 with guard
#define NTHREADS 288
#define NPIX (TY*TX) // 280

#define SIN_ELEMS (SH*SWID*CA)     // 13376 floats
#define WA_ELEMS  (9*CA*FA)        // 21888 floats
#define WB_ELEMS  (9*CA*FB)        // 10944 floats

// ---- scratch (static device memory; no allocation allowed) ----
__device__ float g_h [2*NBATCH*HH*WW*FF];   // hidden state per dir/batch
__device__ float g_z [2*NBATCH*HH*WW*FF];   // update gate scratch
__device__ float g_rh[2*NBATCH*HH*WW*FF];   // r*h scratch
__device__ float g_wA[2*WA_ELEMS];          // packed [dir][k][c][f] weights for gates
__device__ float g_wB[2*WB_ELEMS];          // packed weights for candidate
__device__ float g_bA[2*FA];
__device__ float g_bB[2*FB];

// ---- f32x2 helpers (packed fp32 pairs: full 128 MAC/cyc/SM) ----
__device__ __forceinline__ unsigned long long pack2(float v) {
    unsigned long long r;
    asm("mov.b64 %0, {%1, %1};" : "=l"(r) : "r"(__float_as_uint(v)));
    return r;
}
__device__ __forceinline__ void ffma2(unsigned long long& d, unsigned long long a, unsigned long long b) {
    asm("fma.rn.f32x2 %0, %1, %2, %0;" : "+l"(d) : "l"(a), "l"(b));
}
__device__ __forceinline__ void unpack2(unsigned long long v, float& lo, float& hi) {
    unsigned int a, b;
    asm("mov.b64 {%0, %1}, %2;" : "=r"(a), "=r"(b) : "l"(v));
    lo = __uint_as_float(a); hi = __uint_as_float(b);
}
__device__ __forceinline__ float sigm(float v) {
    return __fdividef(1.0f, 1.0f + __expf(-v));
}

// ---- weight repack: [dir][k=ky*3+kx][c(0..37)][f] with f contiguous ----
__global__ void pack_kernel(const float* __restrict__ WxF, const float* __restrict__ bF,
                            const float* __restrict__ WzrF, const float* __restrict__ WhF,
                            const float* __restrict__ WxB, const float* __restrict__ bB,
                            const float* __restrict__ WzrB, const float* __restrict__ WhB)
{
    const int NWTOT = 2*9*CA*96;
    for (int i = blockIdx.x*blockDim.x + threadIdx.x; i < NWTOT + 2*96; i += gridDim.x*blockDim.x) {
        if (i < NWTOT) {
            int dir = i / (9*CA*96); int r = i - dir*(9*CA*96);
            int k = r / (CA*96);     r -= k*(CA*96);
            int c = r / 96;          int f = r - c*96;
            const float* Wx  = dir ? WxB  : WxF;
            const float* Wzr = dir ? WzrB : WzrF;
            const float* Wh  = dir ? WhB  : WhF;
            float v;
            if (c < CIN)     v = Wx [(k*CIN + c)*96 + f];           // input conv (z,r,h stacked)
            else if (f < 64) v = Wzr[(k*FF + (c-CIN))*64 + f];      // recurrent z,r
            else             v = Wh [(k*FF + (c-CIN))*32 + (f-64)]; // recurrent candidate
            if (f < 64) g_wA[((dir*9 + k)*CA + c)*FA + f]        = v;
            else        g_wB[((dir*9 + k)*CA + c)*FB + (f - 64)] = v;
        } else {
            int j = i - NWTOT;
            int dir = j / 96; int f = j - dir*96;
            const float* bb = dir ? bB : bF;
            if (f < 64) g_bA[dir*FA + f]      = bb[f];
            else        g_bB[dir*FB + f - 64] = bb[f];
        }
    }
}

__global__ void zero_h_kernel() {
    const int n = 2*NBATCH*HH*WW*FF;
    for (int i = blockIdx.x*blockDim.x + threadIdx.x; i < n; i += gridDim.x*blockDim.x)
        g_h[i] = 0.0f;
}

// ---- Kernel A: gates. conv([x_t, h], W_A) -> z, r ; writes g_z, g_rh ----
__global__ void __launch_bounds__(NTHREADS, 1)
stepA(const float* __restrict__ x, int s)
{
    extern __shared__ float sm[];
    float* sIn = sm;                 // SH*SWID*CA
    float* sW  = sm + SIN_ELEMS;     // 9*CA*FA

    const int dir  = blockIdx.z;
    const int b    = blockIdx.y;
    const int tile = blockIdx.x;
    const int ty0  = (tile / TILESX) * TY;
    const int tx0  = (tile % TILESX) * TX;
    const int t    = dir ? (TT - 1 - s) : s;
    const int tid  = threadIdx.x;

    // weights -> smem (float4, uniform-broadcast consumers)
    {
        const float4* src = (const float4*)(g_wA + dir*WA_ELEMS);
        float4* dst = (float4*)sW;
        for (int i = tid; i < WA_ELEMS/4; i += NTHREADS) dst[i] = src[i];
    }
    // input tile [x(6) | h(32)] with zero halo
    {
        const float* xp = x   + (size_t)((b*TT + t)*HH*WW)*CIN;
        const float* hp = g_h + (size_t)((dir*NBATCH + b)*HH*WW)*FF;
        for (int i = tid; i < SIN_ELEMS; i += NTHREADS) {
            int sy = i / (SWID*CA); int r = i - sy*(SWID*CA);
            int sx = r / CA;        int c = r - sx*CA;
            int gy = ty0 + sy - 1, gx = tx0 + sx - 1;
            float v = 0.0f;
            if (gy >= 0 && gy < HH && gx >= 0 && gx < WW)
                v = (c < CIN) ? xp[(gy*WW + gx)*CIN + c]
                              : hp[(gy*WW + gx)*FF + (c - CIN)];
            sIn[i] = v;
        }
    }
    __syncthreads();
    if (tid >= NPIX) return;

    const int py = tid / TX, px = tid - py*TX;

    unsigned long long acc[FA/2];
    {
        const unsigned long long* bb = (const unsigned long long*)(g_bA + dir*FA);
        #pragma unroll
        for (int j = 0; j < FA/2; ++j) acc[j] = bb[j];
    }

    #pragma unroll 1
    for (int ky = 0; ky < 3; ++ky) {
        #pragma unroll 1
        for (int kx = 0; kx < 3; ++kx) {
            const float* ip = sIn + ((py + ky)*SWID + (px + kx))*CA;
            const float* wp = sW + (ky*3 + kx)*CA*FA;
            #pragma unroll 2
            for (int c = 0; c < CA; ++c) {
                unsigned long long v2 = pack2(ip[c]);
                const ulonglong2* w2 = (const ulonglong2*)(wp + c*FA);
                #pragma unroll
                for (int j = 0; j < FA/4; ++j) {
                    ulonglong2 w = w2[j];
                    ffma2(acc[2*j],     v2, w.x);
                    ffma2(acc[2*j + 1], v2, w.y);
                }
            }
        }
    }

    const int gy = ty0 + py, gx = tx0 + px;
    if (gy >= HH) return;
    const int base = ((dir*NBATCH + b)*HH*WW + gy*WW + gx)*FF;
    const float* hin = sIn + ((py + 1)*SWID + (px + 1))*CA + CIN;
    #pragma unroll
    for (int j = 0; j < FF/2; ++j) {
        float z0, z1, r0, r1;
        unpack2(acc[j],         z0, z1);   // f = 2j, 2j+1 (update gate pre-act)
        unpack2(acc[FF/2 + j],  r0, r1);   // f+32       (reset gate pre-act)
        z0 = sigm(z0); z1 = sigm(z1);
        r0 = sigm(r0); r1 = sigm(r1);
        g_z [base + 2*j]     = z0;
        g_z [base + 2*j + 1] = z1;
        g_rh[base + 2*j]     = r0 * hin[2*j];
        g_rh[base + 2*j + 1] = r1 * hin[2*j + 1];
    }
}

// ---- Kernel B: candidate + state update. conv([x_t, r*h], W_B) -> hh; h_new ----
__global__ void __launch_bounds__(NTHREADS, 1)
stepB(const float* __restrict__ x, float* __restrict__ out, int s)
{
    extern __shared__ float sm[];
    float* sIn = sm;                 // SH*SWID*CA
    float* sW  = sm + SIN_ELEMS;     // 9*CA*FB

    const int dir  = blockIdx.z;
    const int b    = blockIdx.y;
    const int tile = blockIdx.x;
    const int ty0  = (tile / TILESX) * TY;
    const int tx0  = (tile % TILESX) * TX;
    const int t    = dir ? (TT - 1 - s) : s;
    const int tid  = threadIdx.x;

    {
        const float4* src = (const float4*)(g_wB + dir*WB_ELEMS);
        float4* dst = (float4*)sW;
        for (int i = tid; i < WB_ELEMS/4; i += NTHREADS) dst[i] = src[i];
    }
    {
        const float* xp  = x    + (size_t)((b*TT + t)*HH*WW)*CIN;
        const float* rhp = g_rh + (size_t)((dir*NBATCH + b)*HH*WW)*FF;
        for (int i = tid; i < SIN_ELEMS; i += NTHREADS) {
            int sy = i / (SWID*CA); int r = i - sy*(SWID*CA);
            int sx = r / CA;        int c = r - sx*CA;
            int gy = ty0 + sy - 1, gx = tx0 + sx - 1;
            float v = 0.0f;
            if (gy >= 0 && gy < HH && gx >= 0 && gx < WW)
                v = (c < CIN) ? xp[(gy*WW + gx)*CIN + c]
                              : rhp[(gy*WW + gx)*FF + (c - CIN)];
            sIn[i] = v;
        }
    }
    __syncthreads();
    if (tid >= NPIX) return;

    const int py = tid / TX, px = tid - py*TX;

    unsigned long long acc[FB/2];
    {
        const unsigned long long* bb = (const unsigned long long*)(g_bB + dir*FB);
        #pragma unroll
        for (int j = 0; j < FB/2; ++j) acc[j] = bb[j];
    }

    #pragma unroll 1
    for (int ky = 0; ky < 3; ++ky) {
        #pragma unroll 1
        for (int kx = 0; kx < 3; ++kx) {
            const float* ip = sIn + ((py + ky)*SWID + (px + kx))*CA;
            const float* wp = sW + (ky*3 + kx)*CA*FB;
            #pragma unroll 2
            for (int c = 0; c < CA; ++c) {
                unsigned long long v2 = pack2(ip[c]);
                const ulonglong2* w2 = (const ulonglong2*)(wp + c*FB);
                #pragma unroll
                for (int j = 0; j < FB/4; ++j) {
                    ulonglong2 w = w2[j];
                    ffma2(acc[2*j],     v2, w.x);
                    ffma2(acc[2*j + 1], v2, w.y);
                }
            }
        }
    }

    const int gy = ty0 + py, gx = tx0 + px;
    if (gy >= HH) return;
    const int base  = ((dir*NBATCH + b)*HH*WW + gy*WW + gx)*FF;
    const int obase = (((b*TT + t)*HH + gy)*WW + gx)*(2*FF) + dir*FF;
    #pragma unroll
    for (int j = 0; j < FB/2; ++j) {
        float p0, p1;
        unpack2(acc[j], p0, p1);
        float hh0 = tanhf(p0), hh1 = tanhf(p1);
        float z0 = g_z[base + 2*j],     z1 = g_z[base + 2*j + 1];
        float h0 = g_h[base + 2*j],     h1 = g_h[base + 2*j + 1];
        float hn0 = z0*h0 + (1.0f - z0)*hh0;
        float hn1 = z1*h1 + (1.0f - z1)*hh1;
        g_h[base + 2*j]     = hn0;
        g_h[base + 2*j + 1] = hn1;
        out[obase + 2*j]     = hn0;
        out[obase + 2*j + 1] = hn1;
    }
}

extern "C" void kernel_launch(void* const* d_in, const int* in_sizes, int n_in,
                              void* d_out, int out_size)
{
    const float* x    = (const float*)d_in[0];
    const float* WxF  = (const float*)d_in[1];
    const float* bF   = (const float*)d_in[2];
    const float* WzrF = (const float*)d_in[3];
    const float* WhF  = (const float*)d_in[4];
    const float* WxB  = (const float*)d_in[5];
    const float* bB   = (const float*)d_in[6];
    const float* WzrB = (const float*)d_in[7];
    const float* WhB  = (const float*)d_in[8];
    float* out = (float*)d_out;

    const int smemA = (SIN_ELEMS + WA_ELEMS) * 4;   // ~141 KB
    const int smemB = (SIN_ELEMS + WB_ELEMS) * 4;   // ~97 KB
    cudaFuncSetAttribute(stepA, cudaFuncAttributeMaxDynamicSharedMemorySize, smemA);
    cudaFuncSetAttribute(stepB, cudaFuncAttributeMaxDynamicSharedMemorySize, smemB);

    pack_kernel<<<64, 256>>>(WxF, bF, WzrF, WhF, WxB, bB, WzrB, WhB);
    zero_h_kernel<<<256, 256>>>();

    dim3 grid(TILESY * TILESX, NBATCH, 2);   // 36 tiles x 2 batch x 2 dir = 144 blocks
    for (int s = 0; s < TT; ++s) {
        stepA<<<grid, NTHREADS, smemA>>>(x, s);
        stepB<<<grid, NTHREADS, smemB>>>(x, out, s);
    }
}

// round 2
// speedup vs baseline: 1.4945x; 1.4945x over previous
#include <cuda_runtime.h>
#include <cstdint>

// Problem constants
#define HH   80
#define WW   120
#define TT   12
#define CIN  6
#define FF   32      // GRU filters per direction
#define NBATCH 2
#define CA   38      // fused input channels: x(6) + state(32)
#define CAP  39      // padded pixel stride (odd -> conflict-free LDS)
#define FA   64      // kernel A outputs: z(32), r(32)
#define FB   32      // kernel B outputs: h-candidate
// Tiling
#define TY   14
#define TX   20
#define SH   (TY+2)  // 16
#define SWID (TX+2)  // 22
#define TILESX 6
#define TILESY 6     // 6*14 = 84 rows, covers 80 with guard
#define NTHREADS 576 // 2 channel-groups x 288
#define NPIX (TY*TX) // 280
#define NHALO (SH*SWID) // 352

#define SIN_ELEMS (NHALO*CAP)      // 13728 floats
#define WA_ELEMS  (9*CA*FA)        // 21888 floats
#define WB_ELEMS  (9*CA*FB)        // 10944 floats

// ---- scratch (static device memory; no allocation allowed) ----
__device__ float g_h [2*NBATCH*HH*WW*FF];   // hidden state per dir/batch
__device__ float g_z [2*NBATCH*HH*WW*FF];   // update gate scratch
__device__ float g_rh[2*NBATCH*HH*WW*FF];   // r*h scratch
__device__ float g_wA[2*WA_ELEMS];          // packed [dir][k][c][f] weights for gates
__device__ float g_wB[2*WB_ELEMS];          // packed weights for candidate
__device__ float g_bA[2*FA];
__device__ float g_bB[2*FB];

// ---- f32x2 helpers ----
__device__ __forceinline__ unsigned long long pack2(float v) {
    unsigned long long r;
    asm("mov.b64 %0, {%1, %1};" : "=l"(r) : "r"(__float_as_uint(v)));
    return r;
}
__device__ __forceinline__ void ffma2(unsigned long long& d, unsigned long long a, unsigned long long b) {
    asm("fma.rn.f32x2 %0, %1, %2, %0;" : "+l"(d) : "l"(a), "l"(b));
}
__device__ __forceinline__ void unpack2(unsigned long long v, float& lo, float& hi) {
    unsigned int a, b;
    asm("mov.b64 {%0, %1}, %2;" : "=r"(a), "=r"(b) : "l"(v));
    lo = __uint_as_float(a); hi = __uint_as_float(b);
}
__device__ __forceinline__ float sigm(float v) {
    return __fdividef(1.0f, 1.0f + __expf(-v));
}
__device__ __forceinline__ float ftanh(float v) {
    float e = __expf(-2.0f * v);
    return __fdividef(1.0f - e, 1.0f + e);
}

// ---- weight repack: [dir][k=ky*3+kx][c(0..37)][f] with f contiguous ----
__global__ void pack_kernel(const float* __restrict__ WxF, const float* __restrict__ bF,
                            const float* __restrict__ WzrF, const float* __restrict__ WhF,
                            const float* __restrict__ WxB, const float* __restrict__ bB,
                            const float* __restrict__ WzrB, const float* __restrict__ WhB)
{
    const int NWTOT = 2*9*CA*96;
    for (int i = blockIdx.x*blockDim.x + threadIdx.x; i < NWTOT + 2*96; i += gridDim.x*blockDim.x) {
        if (i < NWTOT) {
            int dir = i / (9*CA*96); int r = i - dir*(9*CA*96);
            int k = r / (CA*96);     r -= k*(CA*96);
            int c = r / 96;          int f = r - c*96;
            const float* Wx  = dir ? WxB  : WxF;
            const float* Wzr = dir ? WzrB : WzrF;
            const float* Wh  = dir ? WhB  : WhF;
            float v;
            if (c < CIN)     v = Wx [(k*CIN + c)*96 + f];           // input conv (z,r,h stacked)
            else if (f < 64) v = Wzr[(k*FF + (c-CIN))*64 + f];      // recurrent z,r
            else             v = Wh [(k*FF + (c-CIN))*32 + (f-64)]; // recurrent candidate
            if (f < 64) g_wA[((dir*9 + k)*CA + c)*FA + f]        = v;
            else        g_wB[((dir*9 + k)*CA + c)*FB + (f - 64)] = v;
        } else {
            int j = i - NWTOT;
            int dir = j / 96; int f = j - dir*96;
            const float* bb = dir ? bB : bF;
            if (f < 64) g_bA[dir*FA + f]      = bb[f];
            else        g_bB[dir*FB + f - 64] = bb[f];
        }
    }
}

__global__ void zero_h_kernel() {
    const int n = 2*NBATCH*HH*WW*FF;
    for (int i = blockIdx.x*blockDim.x + threadIdx.x; i < n; i += gridDim.x*blockDim.x)
        g_h[i] = 0.0f;
}

// shared tile loader: halo pixel per thread, vector LDG, scalar STS (conflict-free)
__device__ __forceinline__ void load_tile(float* sIn, const float* __restrict__ xp,
                                          const float* __restrict__ hp,
                                          int ty0, int tx0, int tid)
{
    if (tid < NHALO) {
        int sy = tid / SWID, sx = tid - sy*SWID;
        int gy = ty0 + sy - 1, gx = tx0 + sx - 1;
        float* dst = sIn + tid * CAP;
        if (gy >= 0 && gy < HH && gx >= 0 && gx < WW) {
            const float2* x2 = (const float2*)(xp + (gy*WW + gx)*CIN);
            float2 a = x2[0], b = x2[1], c = x2[2];
            dst[0]=a.x; dst[1]=a.y; dst[2]=b.x; dst[3]=b.y; dst[4]=c.x; dst[5]=c.y;
            const float4* h4 = (const float4*)(hp + (gy*WW + gx)*FF);
            #pragma unroll
            for (int j = 0; j < 8; ++j) {
                float4 v = h4[j];
                dst[6+4*j]=v.x; dst[7+4*j]=v.y; dst[8+4*j]=v.z; dst[9+4*j]=v.w;
            }
        } else {
            #pragma unroll
            for (int i = 0; i < CA; ++i) dst[i] = 0.0f;
        }
    }
}

// ---- Kernel A: gates. conv([x_t, h], W_A) -> z, r ; writes g_z, g_rh ----
__global__ void __launch_bounds__(NTHREADS, 1)
stepA(const float* __restrict__ x, int s)
{
    extern __shared__ float sm[];
    float* sIn = sm;                 // NHALO*CAP
    float* sW  = sm + SIN_ELEMS;     // 9*CA*FA

    const int dir  = blockIdx.z;
    const int b    = blockIdx.y;
    const int tile = blockIdx.x;
    const int ty0  = (tile / TILESX) * TY;
    const int tx0  = (tile % TILESX) * TX;
    const int t    = dir ? (TT - 1 - s) : s;
    const int tid  = threadIdx.x;

    // weights -> smem
    {
        const float4* src = (const float4*)(g_wA + dir*WA_ELEMS);
        float4* dst = (float4*)sW;
        for (int i = tid; i < WA_ELEMS/4; i += NTHREADS) dst[i] = src[i];
    }
    load_tile(sIn,
              x   + (size_t)((b*TT + t)*HH*WW)*CIN,
              g_h + (size_t)((dir*NBATCH + b)*HH*WW)*FF,
              ty0, tx0, tid);
    __syncthreads();

    const int g   = tid / 288;        // 0: z-half, 1: r-half (warp-pure)
    const int pix = tid - g*288;
    if (pix >= NPIX) return;
    const int py = pix / TX, px = pix - py*TX;

    unsigned long long acc[16];
    {
        const unsigned long long* bb = (const unsigned long long*)(g_bA + dir*FA + g*32);
        #pragma unroll
        for (int j = 0; j < 16; ++j) acc[j] = bb[j];
    }

    const float* ipbase = sIn + (py*SWID + px)*CAP;
    #pragma unroll 1
    for (int k = 0; k < 9; ++k) {
        const int ky = k / 3, kx = k - ky*3;
        const float* ip = ipbase + (ky*SWID + kx)*CAP;
        const float* wk = sW + k*(CA*FA) + g*32;
        #pragma unroll 2
        for (int c = 0; c < CA; ++c) {
            unsigned long long v2 = pack2(ip[c]);
            const ulonglong2* w2 = (const ulonglong2*)(wk + c*FA);
            #pragma unroll
            for (int j = 0; j < 8; ++j) {
                ulonglong2 w = w2[j];
                ffma2(acc[2*j],     v2, w.x);
                ffma2(acc[2*j + 1], v2, w.y);
            }
        }
    }

    const int gy = ty0 + py, gx = tx0 + px;
    if (gy >= HH) return;
    const int base = ((dir*NBATCH + b)*HH*WW + gy*WW + gx)*FF;
    if (g == 0) {
        float4* zp = (float4*)(g_z + base);
        #pragma unroll
        for (int j = 0; j < 8; ++j) {
            float a0,a1,a2,a3;
            unpack2(acc[2*j],   a0, a1);
            unpack2(acc[2*j+1], a2, a3);
            zp[j] = make_float4(sigm(a0), sigm(a1), sigm(a2), sigm(a3));
        }
    } else {
        const float* hin = ipbase + (SWID + 1)*CAP + CIN;
        float4* rp = (float4*)(g_rh + base);
        #pragma unroll
        for (int j = 0; j < 8; ++j) {
            float a0,a1,a2,a3;
            unpack2(acc[2*j],   a0, a1);
            unpack2(acc[2*j+1], a2, a3);
            rp[j] = make_float4(sigm(a0)*hin[4*j], sigm(a1)*hin[4*j+1],
                                sigm(a2)*hin[4*j+2], sigm(a3)*hin[4*j+3]);
        }
    }
}

// ---- Kernel B: candidate + state update. conv([x_t, r*h], W_B) -> hh; h_new ----
__global__ void __launch_bounds__(NTHREADS, 1)
stepB(const float* __restrict__ x, float* __restrict__ out, int s)
{
    extern __shared__ float sm[];
    float* sIn = sm;                 // NHALO*CAP
    float* sW  = sm + SIN_ELEMS;     // 9*CA*FB

    const int dir  = blockIdx.z;
    const int b    = blockIdx.y;
    const int tile = blockIdx.x;
    const int ty0  = (tile / TILESX) * TY;
    const int tx0  = (tile % TILESX) * TX;
    const int t    = dir ? (TT - 1 - s) : s;
    const int tid  = threadIdx.x;

    {
        const float4* src = (const float4*)(g_wB + dir*WB_ELEMS);
        float4* dst = (float4*)sW;
        for (int i = tid; i < WB_ELEMS/4; i += NTHREADS) dst[i] = src[i];
    }
    load_tile(sIn,
              x    + (size_t)((b*TT + t)*HH*WW)*CIN,
              g_rh + (size_t)((dir*NBATCH + b)*HH*WW)*FF,
              ty0, tx0, tid);
    __syncthreads();

    const int g   = tid / 288;        // f-range [g*16, g*16+16)
    const int pix = tid - g*288;
    if (pix >= NPIX) return;
    const int py = pix / TX, px = pix - py*TX;

    unsigned long long acc[8];
    {
        const unsigned long long* bb = (const unsigned long long*)(g_bB + dir*FB + g*16);
        #pragma unroll
        for (int j = 0; j < 8; ++j) acc[j] = bb[j];
    }

    const float* ipbase = sIn + (py*SWID + px)*CAP;
    #pragma unroll 1
    for (int k = 0; k < 9; ++k) {
        const int ky = k / 3, kx = k - ky*3;
        const float* ip = ipbase + (ky*SWID + kx)*CAP;
        const float* wk = sW + k*(CA*FB) + g*16;
        #pragma unroll 3
        for (int c = 0; c < CA; ++c) {
            unsigned long long v2 = pack2(ip[c]);
            const ulonglong2* w2 = (const ulonglong2*)(wk + c*FB);
            #pragma unroll
            for (int j = 0; j < 4; ++j) {
                ulonglong2 w = w2[j];
                ffma2(acc[2*j],     v2, w.x);
                ffma2(acc[2*j + 1], v2, w.y);
            }
        }
    }

    const int gy = ty0 + py, gx = tx0 + px;
    if (gy >= HH) return;
    const int base  = ((dir*NBATCH + b)*HH*WW + gy*WW + gx)*FF + g*16;
    const int obase = (((b*TT + t)*HH + gy)*WW + gx)*(2*FF) + dir*FF + g*16;
    const float4* zp = (const float4*)(g_z + base);
    const float4* hp = (const float4*)(g_h + base);
    float4* hw = (float4*)(g_h + base);
    float4* ow = (float4*)(out + obase);
    #pragma unroll
    for (int j = 0; j < 4; ++j) {
        float p0,p1,p2,p3;
        unpack2(acc[2*j],   p0, p1);
        unpack2(acc[2*j+1], p2, p3);
        float4 z = zp[j];
        float4 h = hp[j];
        float4 hn;
        hn.x = z.x*h.x + (1.0f - z.x)*ftanh(p0);
        hn.y = z.y*h.y + (1.0f - z.y)*ftanh(p1);
        hn.z = z.z*h.z + (1.0f - z.z)*ftanh(p2);
        hn.w = z.w*h.w + (1.0f - z.w)*ftanh(p3);
        hw[j] = hn;
        ow[j] = hn;
    }
}

extern "C" void kernel_launch(void* const* d_in, const int* in_sizes, int n_in,
                              void* d_out, int out_size)
{
    const float* x    = (const float*)d_in[0];
    const float* WxF  = (const float*)d_in[1];
    const float* bF   = (const float*)d_in[2];
    const float* WzrF = (const float*)d_in[3];
    const float* WhF  = (const float*)d_in[4];
    const float* WxB  = (const float*)d_in[5];
    const float* bB   = (const float*)d_in[6];
    const float* WzrB = (const float*)d_in[7];
    const float* WhB  = (const float*)d_in[8];
    float* out = (float*)d_out;

    const int smemA = (SIN_ELEMS + WA_ELEMS) * 4;   // ~142 KB
    const int smemB = (SIN_ELEMS + WB_ELEMS) * 4;   // ~99 KB
    cudaFuncSetAttribute(stepA, cudaFuncAttributeMaxDynamicSharedMemorySize, smemA);
    cudaFuncSetAttribute(stepB, cudaFuncAttributeMaxDynamicSharedMemorySize, smemB);

    pack_kernel<<<64, 256>>>(WxF, bF, WzrF, WhF, WxB, bB, WzrB, WhB);
    zero_h_kernel<<<256, 256>>>();

    dim3 grid(TILESY * TILESX, NBATCH, 2);   // 36 tiles x 2 batch x 2 dir = 144 blocks
    for (int s = 0; s < TT; ++s) {
        stepA<<<grid, NTHREADS, smemA>>>(x, s);
        stepB<<<grid, NTHREADS, smemB>>>(x, out, s);
    }
}

// round 3
// speedup vs baseline: 1.7390x; 1.1636x over previous
#include <cuda_runtime.h>
#include <cstdint>

// Problem constants
#define HH   80
#define WW   120
#define TT   12
#define CIN  6
#define FF   32      // GRU filters per direction
#define NBATCH 2
#define CA   38      // fused input channels: x(6) + state(32)
#define CAP  39      // padded pixel stride (odd -> conflict-free LDS)
#define FA   64      // kernel A outputs: z(32), r(32)
#define FB   32      // kernel B outputs: h-candidate
// Tiling: 16x20 tile, each thread computes 2 pixels (rows py and py+8)
#define TY   16
#define TX   20
#define SH   (TY+2)  // 18
#define SWID (TX+2)  // 22
#define TILESX 6     // 6*20 = 120 exact
#define TILESY 5     // 5*16 = 80 exact
#define NTHREADS 640
#define NPIX (TY*TX)     // 320
#define PAIRS 160        // pixels per f-group thread (2 px each)
#define NHALO (SH*SWID)  // 396

#define SIN_ELEMS (NHALO*CAP)      // 15444 floats
#define WA_ELEMS  (9*CA*FA)        // 21888 floats
#define WB_ELEMS  (9*CA*FB)        // 10944 floats

// ---- scratch (static device memory; no allocation allowed) ----
__device__ float g_h [2*NBATCH*HH*WW*FF];   // hidden state per dir/batch
__device__ float g_z [2*NBATCH*HH*WW*FF];   // update gate scratch
__device__ float g_rh[2*NBATCH*HH*WW*FF];   // r*h scratch
__device__ float g_wA[2*WA_ELEMS];          // packed [dir][k][c][f] gate weights
__device__ float g_wB[2*WB_ELEMS];          // packed candidate weights
__device__ float g_bA[2*FA];
__device__ float g_bB[2*FB];

// ---- f32x2 helpers ----
__device__ __forceinline__ unsigned long long pack2(float v) {
    unsigned long long r;
    asm("mov.b64 %0, {%1, %1};" : "=l"(r) : "r"(__float_as_uint(v)));
    return r;
}
__device__ __forceinline__ void ffma2(unsigned long long& d, unsigned long long a, unsigned long long b) {
    asm("fma.rn.f32x2 %0, %1, %2, %0;" : "+l"(d) : "l"(a), "l"(b));
}
__device__ __forceinline__ void unpack2(unsigned long long v, float& lo, float& hi) {
    unsigned int a, b;
    asm("mov.b64 {%0, %1}, %2;" : "=r"(a), "=r"(b) : "l"(v));
    lo = __uint_as_float(a); hi = __uint_as_float(b);
}
__device__ __forceinline__ float sigm(float v) {
    return __fdividef(1.0f, 1.0f + __expf(-v));
}
__device__ __forceinline__ float ftanh(float v) {
    float e = __expf(-2.0f * v);
    return __fdividef(1.0f - e, 1.0f + e);
}

// ---- weight repack: [dir][k=ky*3+kx][c(0..37)][f] with f contiguous ----
__global__ void pack_kernel(const float* __restrict__ WxF, const float* __restrict__ bF,
                            const float* __restrict__ WzrF, const float* __restrict__ WhF,
                            const float* __restrict__ WxB, const float* __restrict__ bB,
                            const float* __restrict__ WzrB, const float* __restrict__ WhB)
{
    const int NWTOT = 2*9*CA*96;
    for (int i = blockIdx.x*blockDim.x + threadIdx.x; i < NWTOT + 2*96; i += gridDim.x*blockDim.x) {
        if (i < NWTOT) {
            int dir = i / (9*CA*96); int r = i - dir*(9*CA*96);
            int k = r / (CA*96);     r -= k*(CA*96);
            int c = r / 96;          int f = r - c*96;
            const float* Wx  = dir ? WxB  : WxF;
            const float* Wzr = dir ? WzrB : WzrF;
            const float* Wh  = dir ? WhB  : WhF;
            float v;
            if (c < CIN)     v = Wx [(k*CIN + c)*96 + f];
            else if (f < 64) v = Wzr[(k*FF + (c-CIN))*64 + f];
            else             v = Wh [(k*FF + (c-CIN))*32 + (f-64)];
            if (f < 64) g_wA[((dir*9 + k)*CA + c)*FA + f]        = v;
            else        g_wB[((dir*9 + k)*CA + c)*FB + (f - 64)] = v;
        } else {
            int j = i - NWTOT;
            int dir = j / 96; int f = j - dir*96;
            const float* bb = dir ? bB : bF;
            if (f < 64) g_bA[dir*FA + f]      = bb[f];
            else        g_bB[dir*FB + f - 64] = bb[f];
        }
    }
}

__global__ void zero_h_kernel() {
    const int n = 2*NBATCH*HH*WW*FF;
    for (int i = blockIdx.x*blockDim.x + threadIdx.x; i < n; i += gridDim.x*blockDim.x)
        g_h[i] = 0.0f;
}

// shared tile loader: one halo pixel per thread, vector LDG, scalar STS
__device__ __forceinline__ void load_tile(float* sIn, const float* __restrict__ xp,
                                          const float* __restrict__ hp,
                                          int ty0, int tx0, int tid)
{
    if (tid < NHALO) {
        int sy = tid / SWID, sx = tid - sy*SWID;
        int gy = ty0 + sy - 1, gx = tx0 + sx - 1;
        float* dst = sIn + tid * CAP;
        if (gy >= 0 && gy < HH && gx >= 0 && gx < WW) {
            const float2* x2 = (const float2*)(xp + (gy*WW + gx)*CIN);
            float2 a = x2[0], b = x2[1], c = x2[2];
            dst[0]=a.x; dst[1]=a.y; dst[2]=b.x; dst[3]=b.y; dst[4]=c.x; dst[5]=c.y;
            const float4* h4 = (const float4*)(hp + (gy*WW + gx)*FF);
            #pragma unroll
            for (int j = 0; j < 8; ++j) {
                float4 v = h4[j];
                dst[6+4*j]=v.x; dst[7+4*j]=v.y; dst[8+4*j]=v.z; dst[9+4*j]=v.w;
            }
        } else {
            #pragma unroll
            for (int i = 0; i < CA; ++i) dst[i] = 0.0f;
        }
    }
}

// ---- Kernel A: gates. conv([x_t, h], W_A) -> z, r ; writes g_z, g_rh ----
// 4 warp-pure f-groups of 16 channels; each thread: 2 pixels.
__global__ void __launch_bounds__(NTHREADS, 1)
stepA(const float* __restrict__ x, int s)
{
    extern __shared__ float sm[];
    float* sIn = sm;                 // NHALO*CAP
    float* sW  = sm + SIN_ELEMS;     // 9*CA*FA

    const int dir  = blockIdx.z;
    const int b    = blockIdx.y;
    const int tile = blockIdx.x;
    const int ty0  = (tile / TILESX) * TY;
    const int tx0  = (tile % TILESX) * TX;
    const int t    = dir ? (TT - 1 - s) : s;
    const int tid  = threadIdx.x;

    {
        const float4* src = (const float4*)(g_wA + dir*WA_ELEMS);
        float4* dst = (float4*)sW;
        for (int i = tid; i < WA_ELEMS/4; i += NTHREADS) dst[i] = src[i];
    }
    load_tile(sIn,
              x   + (size_t)((b*TT + t)*HH*WW)*CIN,
              g_h + (size_t)((dir*NBATCH + b)*HH*WW)*FF,
              ty0, tx0, tid);
    __syncthreads();

    const int g   = tid / PAIRS;          // f-group 0..3 (warp-pure: 160 = 5 warps)
    const int pid = tid - g*PAIRS;        // 0..159
    const int py  = pid / TX, px = pid - py*TX;   // py 0..7; second pixel at py+8

    unsigned long long acc0[8], acc1[8];
    {
        const unsigned long long* bb = (const unsigned long long*)(g_bA + dir*FA + g*16);
        #pragma unroll
        for (int j = 0; j < 8; ++j) { acc0[j] = bb[j]; acc1[j] = bb[j]; }
    }

    const float* ipb = sIn + (py*SWID + px)*CAP;
    #pragma unroll 1
    for (int k = 0; k < 9; ++k) {
        const int ky = k / 3, kx = k - ky*3;
        const float* ip0 = ipb + (ky*SWID + kx)*CAP;
        const float* ip1 = ip0 + 8*SWID*CAP;
        const float* wk  = sW + k*(CA*FA) + g*16;
        #pragma unroll 2
        for (int c = 0; c < CA; ++c) {
            unsigned long long v0 = pack2(ip0[c]);
            unsigned long long v1 = pack2(ip1[c]);
            const ulonglong2* w2 = (const ulonglong2*)(wk + c*FA);
            #pragma unroll
            for (int j = 0; j < 4; ++j) {
                ulonglong2 w = w2[j];
                ffma2(acc0[2*j],   v0, w.x);
                ffma2(acc0[2*j+1], v0, w.y);
                ffma2(acc1[2*j],   v1, w.x);
                ffma2(acc1[2*j+1], v1, w.y);
            }
        }
    }

    const int gx = tx0 + px;
    #pragma unroll
    for (int pp = 0; pp < 2; ++pp) {
        const int gy = ty0 + py + 8*pp;
        const unsigned long long* acc = pp ? acc1 : acc0;
        const int base = ((dir*NBATCH + b)*HH*WW + gy*WW + gx)*FF;
        if (g < 2) {   // z channels [16g, 16g+16)
            float4* zp = (float4*)(g_z + base + 16*g);
            #pragma unroll
            for (int j = 0; j < 4; ++j) {
                float a0,a1,a2,a3;
                unpack2(acc[2*j],   a0, a1);
                unpack2(acc[2*j+1], a2, a3);
                zp[j] = make_float4(sigm(a0), sigm(a1), sigm(a2), sigm(a3));
            }
        } else {       // r channels [16(g-2), ...)
            const int rf = 16*(g - 2);
            const float* hin = sIn + ((py + 8*pp + 1)*SWID + (px + 1))*CAP + CIN + rf;
            float4* rp = (float4*)(g_rh + base + rf);
            #pragma unroll
            for (int j = 0; j < 4; ++j) {
                float a0,a1,a2,a3;
                unpack2(acc[2*j],   a0, a1);
                unpack2(acc[2*j+1], a2, a3);
                rp[j] = make_float4(sigm(a0)*hin[4*j],   sigm(a1)*hin[4*j+1],
                                    sigm(a2)*hin[4*j+2], sigm(a3)*hin[4*j+3]);
            }
        }
    }
}

// ---- Kernel B: candidate + state update. conv([x_t, r*h], W_B) -> hh; h_new ----
// 4 warp-pure f-groups of 8 channels; each thread: 2 pixels.
__global__ void __launch_bounds__(NTHREADS, 1)
stepB(const float* __restrict__ x, float* __restrict__ out, int s)
{
    extern __shared__ float sm[];
    float* sIn = sm;                 // NHALO*CAP
    float* sW  = sm + SIN_ELEMS;     // 9*CA*FB

    const int dir  = blockIdx.z;
    const int b    = blockIdx.y;
    const int tile = blockIdx.x;
    const int ty0  = (tile / TILESX) * TY;
    const int tx0  = (tile % TILESX) * TX;
    const int t    = dir ? (TT - 1 - s) : s;
    const int tid  = threadIdx.x;

    {
        const float4* src = (const float4*)(g_wB + dir*WB_ELEMS);
        float4* dst = (float4*)sW;
        for (int i = tid; i < WB_ELEMS/4; i += NTHREADS) dst[i] = src[i];
    }
    load_tile(sIn,
              x    + (size_t)((b*TT + t)*HH*WW)*CIN,
              g_rh + (size_t)((dir*NBATCH + b)*HH*WW)*FF,
              ty0, tx0, tid);
    __syncthreads();

    const int g   = tid / PAIRS;          // f-group 0..3, channels [8g, 8g+8)
    const int pid = tid - g*PAIRS;
    const int py  = pid / TX, px = pid - py*TX;

    unsigned long long acc0[4], acc1[4];
    {
        const unsigned long long* bb = (const unsigned long long*)(g_bB + dir*FB + g*8);
        #pragma unroll
        for (int j = 0; j < 4; ++j) { acc0[j] = bb[j]; acc1[j] = bb[j]; }
    }

    const float* ipb = sIn + (py*SWID + px)*CAP;
    #pragma unroll 1
    for (int k = 0; k < 9; ++k) {
        const int ky = k / 3, kx = k - ky*3;
        const float* ip0 = ipb + (ky*SWID + kx)*CAP;
        const float* ip1 = ip0 + 8*SWID*CAP;
        const float* wk  = sW + k*(CA*FB) + g*8;
        #pragma unroll 2
        for (int c = 0; c < CA; ++c) {
            unsigned long long v0 = pack2(ip0[c]);
            unsigned long long v1 = pack2(ip1[c]);
            const ulonglong2* w2 = (const ulonglong2*)(wk + c*FB);
            #pragma unroll
            for (int j = 0; j < 2; ++j) {
                ulonglong2 w = w2[j];
                ffma2(acc0[2*j],   v0, w.x);
                ffma2(acc0[2*j+1], v0, w.y);
                ffma2(acc1[2*j],   v1, w.x);
                ffma2(acc1[2*j+1], v1, w.y);
            }
        }
    }

    const int gx = tx0 + px;
    #pragma unroll
    for (int pp = 0; pp < 2; ++pp) {
        const int gy = ty0 + py + 8*pp;
        const unsigned long long* acc = pp ? acc1 : acc0;
        const int base  = ((dir*NBATCH + b)*HH*WW + gy*WW + gx)*FF + 8*g;
        const int obase = (((b*TT + t)*HH + gy)*WW + gx)*(2*FF) + dir*FF + 8*g;
        const float4* zp = (const float4*)(g_z + base);
        const float4* hp = (const float4*)(g_h + base);
        float4* hw = (float4*)(g_h + base);
        float4* ow = (float4*)(out + obase);
        #pragma unroll
        for (int j = 0; j < 2; ++j) {
            float p0,p1,p2,p3;
            unpack2(acc[2*j],   p0, p1);
            unpack2(acc[2*j+1], p2, p3);
            float4 z = zp[j];
            float4 h = hp[j];
            float4 hn;
            hn.x = z.x*h.x + (1.0f - z.x)*ftanh(p0);
            hn.y = z.y*h.y + (1.0f - z.y)*ftanh(p1);
            hn.z = z.z*h.z + (1.0f - z.z)*ftanh(p2);
            hn.w = z.w*h.w + (1.0f - z.w)*ftanh(p3);
            hw[j] = hn;
            ow[j] = hn;
        }
    }
}

extern "C" void kernel_launch(void* const* d_in, const int* in_sizes, int n_in,
                              void* d_out, int out_size)
{
    const float* x    = (const float*)d_in[0];
    const float* WxF  = (const float*)d_in[1];
    const float* bF   = (const float*)d_in[2];
    const float* WzrF = (const float*)d_in[3];
    const float* WhF  = (const float*)d_in[4];
    const float* WxB  = (const float*)d_in[5];
    const float* bB   = (const float*)d_in[6];
    const float* WzrB = (const float*)d_in[7];
    const float* WhB  = (const float*)d_in[8];
    float* out = (float*)d_out;

    const int smemA = (SIN_ELEMS + WA_ELEMS) * 4;   // ~149 KB
    const int smemB = (SIN_ELEMS + WB_ELEMS) * 4;   // ~106 KB
    cudaFuncSetAttribute(stepA, cudaFuncAttributeMaxDynamicSharedMemorySize, smemA);
    cudaFuncSetAttribute(stepB, cudaFuncAttributeMaxDynamicSharedMemorySize, smemB);

    pack_kernel<<<64, 256>>>(WxF, bF, WzrF, WhF, WxB, bB, WzrB, WhB);
    zero_h_kernel<<<256, 256>>>();

    dim3 grid(TILESY * TILESX, NBATCH, 2);   // 30 tiles x 2 batch x 2 dir = 120 blocks
    for (int s = 0; s < TT; ++s) {
        stepA<<<grid, NTHREADS, smemA>>>(x, s);
        stepB<<<grid, NTHREADS, smemB>>>(x, out, s);
    }
}

// round 4
// speedup vs baseline: 1.7682x; 1.0168x over previous
#include <cuda_runtime.h>
#include <cstdint>

// Problem constants
#define HH   80
#define WW   120
#define TT   12
#define CIN  6
#define FF   32      // GRU filters per direction
#define NBATCH 2
#define CA   38      // fused input channels: x(6) + state(32)
#define CAP  39      // padded pixel stride (odd -> conflict-free LDS)
#define FA   64      // kernel A outputs: z(32), r(32)
#define FB   32      // kernel B outputs: h-candidate
// Tiling: 16x20 tile, each thread computes 2 pixels (rows py and py+8)
#define TY   16
#define TX   20
#define SH   (TY+2)  // 18
#define SWID (TX+2)  // 22
#define TILESX 6     // 6*20 = 120 exact
#define TILESY 5     // 5*16 = 80 exact
#define NTHREADS 640
#define PAIRS 160        // pixel-slots per f-group (2 px each)
#define NHALO (SH*SWID)  // 396

#define SIN_ELEMS (NHALO*CAP)      // 15444 floats
#define WA_ELEMS  (9*CA*FA)        // 21888 floats
#define WB_ELEMS  (9*CA*FB)        // 10944 floats

// ---- scratch (static device memory; no allocation allowed) ----
__device__ float g_h [2*NBATCH*HH*WW*FF];   // hidden state per dir/batch
__device__ float g_z [2*NBATCH*HH*WW*FF];   // update gate scratch
__device__ float g_rh[2*NBATCH*HH*WW*FF];   // r*h scratch
__device__ float g_wA[2*WA_ELEMS];          // packed [dir][k][c][f] gate weights
__device__ float g_wB[2*WB_ELEMS];          // packed candidate weights
__device__ float g_bA[2*FA];
__device__ float g_bB[2*FB];

// ---- f32x2 helpers ----
__device__ __forceinline__ unsigned long long pack2(float v) {
    unsigned long long r;
    asm("mov.b64 %0, {%1, %1};" : "=l"(r) : "r"(__float_as_uint(v)));
    return r;
}
__device__ __forceinline__ void ffma2(unsigned long long& d, unsigned long long a, unsigned long long b) {
    asm("fma.rn.f32x2 %0, %1, %2, %0;" : "+l"(d) : "l"(a), "l"(b));
}
__device__ __forceinline__ void unpack2(unsigned long long v, float& lo, float& hi) {
    unsigned int a, b;
    asm("mov.b64 {%0, %1}, %2;" : "=r"(a), "=r"(b) : "l"(v));
    lo = __uint_as_float(a); hi = __uint_as_float(b);
}
__device__ __forceinline__ float sigm(float v) {
    return __fdividef(1.0f, 1.0f + __expf(-v));
}
__device__ __forceinline__ float ftanh(float v) {
    float e = __expf(-2.0f * v);
    return __fdividef(1.0f - e, 1.0f + e);
}

// ---- weight repack: [dir][k=ky*3+kx][c(0..37)][f] with f contiguous ----
__global__ void pack_kernel(const float* __restrict__ WxF, const float* __restrict__ bF,
                            const float* __restrict__ WzrF, const float* __restrict__ WhF,
                            const float* __restrict__ WxB, const float* __restrict__ bB,
                            const float* __restrict__ WzrB, const float* __restrict__ WhB)
{
    const int NWTOT = 2*9*CA*96;
    for (int i = blockIdx.x*blockDim.x + threadIdx.x; i < NWTOT + 2*96; i += gridDim.x*blockDim.x) {
        if (i < NWTOT) {
            int dir = i / (9*CA*96); int r = i - dir*(9*CA*96);
            int k = r / (CA*96);     r -= k*(CA*96);
            int c = r / 96;          int f = r - c*96;
            const float* Wx  = dir ? WxB  : WxF;
            const float* Wzr = dir ? WzrB : WzrF;
            const float* Wh  = dir ? WhB  : WhF;
            float v;
            if (c < CIN)     v = Wx [(k*CIN + c)*96 + f];
            else if (f < 64) v = Wzr[(k*FF + (c-CIN))*64 + f];
            else             v = Wh [(k*FF + (c-CIN))*32 + (f-64)];
            if (f < 64) g_wA[((dir*9 + k)*CA + c)*FA + f]        = v;
            else        g_wB[((dir*9 + k)*CA + c)*FB + (f - 64)] = v;
        } else {
            int j = i - NWTOT;
            int dir = j / 96; int f = j - dir*96;
            const float* bb = dir ? bB : bF;
            if (f < 64) g_bA[dir*FA + f]      = bb[f];
            else        g_bB[dir*FB + f - 64] = bb[f];
        }
    }
}

__global__ void zero_h_kernel() {
    const int n = 2*NBATCH*HH*WW*FF;
    for (int i = blockIdx.x*blockDim.x + threadIdx.x; i < n; i += gridDim.x*blockDim.x)
        g_h[i] = 0.0f;
}

// shared tile loader: one halo pixel per thread, vector LDG, scalar STS
__device__ __forceinline__ void load_tile(float* sIn, const float* __restrict__ xp,
                                          const float* __restrict__ hp,
                                          int ty0, int tx0, int tid)
{
    if (tid < NHALO) {
        int sy = tid / SWID, sx = tid - sy*SWID;
        int gy = ty0 + sy - 1, gx = tx0 + sx - 1;
        float* dst = sIn + tid * CAP;
        if (gy >= 0 && gy < HH && gx >= 0 && gx < WW) {
            const float2* x2 = (const float2*)(xp + (gy*WW + gx)*CIN);
            float2 a = x2[0], b = x2[1], c = x2[2];
            dst[0]=a.x; dst[1]=a.y; dst[2]=b.x; dst[3]=b.y; dst[4]=c.x; dst[5]=c.y;
            const float4* h4 = (const float4*)(hp + (gy*WW + gx)*FF);
            #pragma unroll
            for (int j = 0; j < 8; ++j) {
                float4 v = h4[j];
                dst[6+4*j]=v.x; dst[7+4*j]=v.y; dst[8+4*j]=v.z; dst[9+4*j]=v.w;
            }
        } else {
            #pragma unroll
            for (int i = 0; i < CA; ++i) dst[i] = 0.0f;
        }
    }
}

// ---- Kernel A: gates. conv([x_t, h], W_A) -> z, r ; writes g_z, g_rh ----
// 4 warp-pure f-groups of 16 channels; each thread: 2 pixels. Fully unrolled c.
__global__ void __launch_bounds__(NTHREADS, 1)
stepA(const float* __restrict__ x, int s)
{
    extern __shared__ float sm[];
    float* sIn = sm;                 // NHALO*CAP
    float* sW  = sm + SIN_ELEMS;     // 9*CA*FA

    const int dir  = blockIdx.z;
    const int b    = blockIdx.y;
    const int tile = blockIdx.x;
    const int ty0  = (tile / TILESX) * TY;
    const int tx0  = (tile % TILESX) * TX;
    const int t    = dir ? (TT - 1 - s) : s;
    const int tid  = threadIdx.x;

    {
        const float4* src = (const float4*)(g_wA + dir*WA_ELEMS);
        float4* dst = (float4*)sW;
        for (int i = tid; i < WA_ELEMS/4; i += NTHREADS) dst[i] = src[i];
    }
    load_tile(sIn,
              x   + (size_t)((b*TT + t)*HH*WW)*CIN,
              g_h + (size_t)((dir*NBATCH + b)*HH*WW)*FF,
              ty0, tx0, tid);
    __syncthreads();

    const int g   = tid / PAIRS;          // f-group 0..3 (warp-pure: 160 = 5 warps)
    const int pid = tid - g*PAIRS;        // 0..159
    const int py  = pid / TX, px = pid - py*TX;   // py 0..7; second pixel at py+8

    unsigned long long acc0[8], acc1[8];
    {
        const unsigned long long* bb = (const unsigned long long*)(g_bA + dir*FA + g*16);
        #pragma unroll
        for (int j = 0; j < 8; ++j) { acc0[j] = bb[j]; acc1[j] = bb[j]; }
    }

    const float* ipb = sIn + (py*SWID + px)*CAP;
    const float* wgb = sW + g*16;
    #pragma unroll 1
    for (int k = 0; k < 9; ++k) {
        const int ky = k / 3, kx = k - ky*3;
        const float* ip0 = ipb + (ky*SWID + kx)*CAP;
        const float* ip1 = ip0 + 8*SWID*CAP;
        const float* wk  = wgb + k*(CA*FA);
        #pragma unroll
        for (int c = 0; c < CA; ++c) {
            unsigned long long v0 = pack2(ip0[c]);
            unsigned long long v1 = pack2(ip1[c]);
            const ulonglong2* w2 = (const ulonglong2*)(wk + c*FA);
            #pragma unroll
            for (int j = 0; j < 4; ++j) {
                ulonglong2 w = w2[j];
                ffma2(acc0[2*j],   v0, w.x);
                ffma2(acc0[2*j+1], v0, w.y);
                ffma2(acc1[2*j],   v1, w.x);
                ffma2(acc1[2*j+1], v1, w.y);
            }
        }
    }

    const int gx = tx0 + px;
    #pragma unroll
    for (int pp = 0; pp < 2; ++pp) {
        const int gy = ty0 + py + 8*pp;
        const unsigned long long* acc = pp ? acc1 : acc0;
        const int base = ((dir*NBATCH + b)*HH*WW + gy*WW + gx)*FF;
        if (g < 2) {   // z channels [16g, 16g+16)
            float4* zp = (float4*)(g_z + base + 16*g);
            #pragma unroll
            for (int j = 0; j < 4; ++j) {
                float a0,a1,a2,a3;
                unpack2(acc[2*j],   a0, a1);
                unpack2(acc[2*j+1], a2, a3);
                zp[j] = make_float4(sigm(a0), sigm(a1), sigm(a2), sigm(a3));
            }
        } else {       // r channels [16(g-2), ...)
            const int rf = 16*(g - 2);
            const float* hin = sIn + ((py + 8*pp + 1)*SWID + (px + 1))*CAP + CIN + rf;
            float4* rp = (float4*)(g_rh + base + rf);
            #pragma unroll
            for (int j = 0; j < 4; ++j) {
                float a0,a1,a2,a3;
                unpack2(acc[2*j],   a0, a1);
                unpack2(acc[2*j+1], a2, a3);
                rp[j] = make_float4(sigm(a0)*hin[4*j],   sigm(a1)*hin[4*j+1],
                                    sigm(a2)*hin[4*j+2], sigm(a3)*hin[4*j+3]);
            }
        }
    }
}

// ---- Kernel B: candidate + state update. conv([x_t, r*h], W_B) -> hh; h_new ----
// 4 warp-pure f-groups of 8 channels; each thread: 2 pixels. Fully unrolled c.
__global__ void __launch_bounds__(NTHREADS, 1)
stepB(const float* __restrict__ x, float* __restrict__ out, int s)
{
    extern __shared__ float sm[];
    float* sIn = sm;                 // NHALO*CAP
    float* sW  = sm + SIN_ELEMS;     // 9*CA*FB

    const int dir  = blockIdx.z;
    const int b    = blockIdx.y;
    const int tile = blockIdx.x;
    const int ty0  = (tile / TILESX) * TY;
    const int tx0  = (tile % TILESX) * TX;
    const int t    = dir ? (TT - 1 - s) : s;
    const int tid  = threadIdx.x;

    {
        const float4* src = (const float4*)(g_wB + dir*WB_ELEMS);
        float4* dst = (float4*)sW;
        for (int i = tid; i < WB_ELEMS/4; i += NTHREADS) dst[i] = src[i];
    }
    load_tile(sIn,
              x    + (size_t)((b*TT + t)*HH*WW)*CIN,
              g_rh + (size_t)((dir*NBATCH + b)*HH*WW)*FF,
              ty0, tx0, tid);
    __syncthreads();

    const int g   = tid / PAIRS;          // f-group 0..3, channels [8g, 8g+8)
    const int pid = tid - g*PAIRS;
    const int py  = pid / TX, px = pid - py*TX;

    unsigned long long acc0[4], acc1[4];
    {
        const unsigned long long* bb = (const unsigned long long*)(g_bB + dir*FB + g*8);
        #pragma unroll
        for (int j = 0; j < 4; ++j) { acc0[j] = bb[j]; acc1[j] = bb[j]; }
    }

    const float* ipb = sIn + (py*SWID + px)*CAP;
    const float* wgb = sW + g*8;
    #pragma unroll 1
    for (int k = 0; k < 9; ++k) {
        const int ky = k / 3, kx = k - ky*3;
        const float* ip0 = ipb + (ky*SWID + kx)*CAP;
        const float* ip1 = ip0 + 8*SWID*CAP;
        const float* wk  = wgb + k*(CA*FB);
        #pragma unroll
        for (int c = 0; c < CA; ++c) {
            unsigned long long v0 = pack2(ip0[c]);
            unsigned long long v1 = pack2(ip1[c]);
            const ulonglong2* w2 = (const ulonglong2*)(wk + c*FB);
            #pragma unroll
            for (int j = 0; j < 2; ++j) {
                ulonglong2 w = w2[j];
                ffma2(acc0[2*j],   v0, w.x);
                ffma2(acc0[2*j+1], v0, w.y);
                ffma2(acc1[2*j],   v1, w.x);
                ffma2(acc1[2*j+1], v1, w.y);
            }
        }
    }

    const int gx = tx0 + px;
    #pragma unroll
    for (int pp = 0; pp < 2; ++pp) {
        const int gy = ty0 + py + 8*pp;
        const unsigned long long* acc = pp ? acc1 : acc0;
        const int base  = ((dir*NBATCH + b)*HH*WW + gy*WW + gx)*FF + 8*g;
        const int obase = (((b*TT + t)*HH + gy)*WW + gx)*(2*FF) + dir*FF + 8*g;
        const float4* zp = (const float4*)(g_z + base);
        const float4* hp = (const float4*)(g_h + base);
        float4* hw = (float4*)(g_h + base);
        float4* ow = (float4*)(out + obase);
        #pragma unroll
        for (int j = 0; j < 2; ++j) {
            float p0,p1,p2,p3;
            unpack2(acc[2*j],   p0, p1);
            unpack2(acc[2*j+1], p2, p3);
            float4 z = zp[j];
            float4 h = hp[j];
            float4 hn;
            hn.x = z.x*h.x + (1.0f - z.x)*ftanh(p0);
            hn.y = z.y*h.y + (1.0f - z.y)*ftanh(p1);
            hn.z = z.z*h.z + (1.0f - z.z)*ftanh(p2);
            hn.w = z.w*h.w + (1.0f - z.w)*ftanh(p3);
            hw[j] = hn;
            ow[j] = hn;
        }
    }
}

extern "C" void kernel_launch(void* const* d_in, const int* in_sizes, int n_in,
                              void* d_out, int out_size)
{
    const float* x    = (const float*)d_in[0];
    const float* WxF  = (const float*)d_in[1];
    const float* bF   = (const float*)d_in[2];
    const float* WzrF = (const float*)d_in[3];
    const float* WhF  = (const float*)d_in[4];
    const float* WxB  = (const float*)d_in[5];
    const float* bB   = (const float*)d_in[6];
    const float* WzrB = (const float*)d_in[7];
    const float* WhB  = (const float*)d_in[8];
    float* out = (float*)d_out;

    const int smemA = (SIN_ELEMS + WA_ELEMS) * 4;   // ~149 KB
    const int smemB = (SIN_ELEMS + WB_ELEMS) * 4;   // ~106 KB
    cudaFuncSetAttribute(stepA, cudaFuncAttributeMaxDynamicSharedMemorySize, smemA);
    cudaFuncSetAttribute(stepB, cudaFuncAttributeMaxDynamicSharedMemorySize, smemB);

    pack_kernel<<<64, 256>>>(WxF, bF, WzrF, WhF, WxB, bB, WzrB, WhB);
    zero_h_kernel<<<256, 256>>>();

    dim3 grid(TILESY * TILESX, NBATCH, 2);   // 30 tiles x 2 batch x 2 dir = 120 blocks
    for (int s = 0; s < TT; ++s) {
        stepA<<<grid, NTHREADS, smemA>>>(x, s);
        stepB<<<grid, NTHREADS, smemB>>>(x, out, s);
    }
}

// round 5
// speedup vs baseline: 1.8933x; 1.0708x over previous
#include <cuda_runtime.h>
#include <cstdint>

// Problem constants
#define HH   80
#define WW   120
#define TT   12
#define CIN  6
#define FF   32      // GRU filters per direction
#define NBATCH 2
#define CA   38      // real fused channels: x(6) + state(32)
#define CA_P 40      // padded channel count (zeros at 38,39)
#define CAP  44      // padded pixel stride in floats (16B-aligned, conflict-free LDS.128)
#define FA   64      // kernel A outputs: z(32), r(32)
#define FB   32      // kernel B outputs: h-candidate
// Tiling: 16x20 tile, each thread computes 2 pixels (rows py and py+8)
#define TY   16
#define TX   20
#define SH   (TY+2)  // 18
#define SWID (TX+2)  // 22
#define TILESX 6     // 6*20 = 120 exact
#define TILESY 5     // 5*16 = 80 exact
#define NTHREADS 640
#define PAIRS 160        // pixel-slots per f-group (2 px each)
#define NHALO (SH*SWID)  // 396

#define SIN_ELEMS (NHALO*CAP)      // 17424 floats (69.7 KB)
#define WA_ELEMS  (9*CA_P*FA)      // 23040 floats (92.2 KB)
#define WB_ELEMS  (9*CA_P*FB)      // 11520 floats (46.1 KB)

// ---- scratch (static device memory; no allocation allowed) ----
__device__ float g_h [2*NBATCH*HH*WW*FF];   // hidden state per dir/batch
__device__ float g_z [2*NBATCH*HH*WW*FF];   // update gate scratch
__device__ float g_rh[2*NBATCH*HH*WW*FF];   // r*h scratch
__device__ float g_wA[2*WA_ELEMS];          // packed [dir][k][c][f] gate weights (c padded)
__device__ float g_wB[2*WB_ELEMS];          // packed candidate weights (c padded)
__device__ float g_bA[2*FA];
__device__ float g_bB[2*FB];

// ---- f32x2 helpers ----
__device__ __forceinline__ unsigned long long pack2(float v) {
    unsigned long long r;
    asm("mov.b64 %0, {%1, %1};" : "=l"(r) : "r"(__float_as_uint(v)));
    return r;
}
__device__ __forceinline__ void ffma2(unsigned long long& d, unsigned long long a, unsigned long long b) {
    asm("fma.rn.f32x2 %0, %1, %2, %0;" : "+l"(d) : "l"(a), "l"(b));
}
__device__ __forceinline__ void unpack2(unsigned long long v, float& lo, float& hi) {
    unsigned int a, b;
    asm("mov.b64 {%0, %1}, %2;" : "=r"(a), "=r"(b) : "l"(v));
    lo = __uint_as_float(a); hi = __uint_as_float(b);
}
__device__ __forceinline__ float sigm(float v) {
    return __fdividef(1.0f, 1.0f + __expf(-v));
}
__device__ __forceinline__ float ftanh(float v) {
    float e = __expf(-2.0f * v);
    return __fdividef(1.0f - e, 1.0f + e);
}

// ---- weight repack: [dir][k][c(0..39)][f], zero-pad c=38,39 ----
__global__ void pack_kernel(const float* __restrict__ WxF, const float* __restrict__ bF,
                            const float* __restrict__ WzrF, const float* __restrict__ WhF,
                            const float* __restrict__ WxB, const float* __restrict__ bB,
                            const float* __restrict__ WzrB, const float* __restrict__ WhB)
{
    const int NWTOT = 2*9*CA_P*96;
    for (int i = blockIdx.x*blockDim.x + threadIdx.x; i < NWTOT + 2*96; i += gridDim.x*blockDim.x) {
        if (i < NWTOT) {
            int dir = i / (9*CA_P*96); int r = i - dir*(9*CA_P*96);
            int k = r / (CA_P*96);     r -= k*(CA_P*96);
            int c = r / 96;            int f = r - c*96;
            const float* Wx  = dir ? WxB  : WxF;
            const float* Wzr = dir ? WzrB : WzrF;
            const float* Wh  = dir ? WhB  : WhF;
            float v;
            if (c >= CA)     v = 0.0f;                              // channel padding
            else if (c < CIN)     v = Wx [(k*CIN + c)*96 + f];
            else if (f < 64) v = Wzr[(k*FF + (c-CIN))*64 + f];
            else             v = Wh [(k*FF + (c-CIN))*32 + (f-64)];
            if (f < 64) g_wA[((dir*9 + k)*CA_P + c)*FA + f]        = v;
            else        g_wB[((dir*9 + k)*CA_P + c)*FB + (f - 64)] = v;
        } else {
            int j = i - NWTOT;
            int dir = j / 96; int f = j - dir*96;
            const float* bb = dir ? bB : bF;
            if (f < 64) g_bA[dir*FA + f]      = bb[f];
            else        g_bB[dir*FB + f - 64] = bb[f];
        }
    }
}

__global__ void zero_h_kernel() {
    const int n = 2*NBATCH*HH*WW*FF;
    for (int i = blockIdx.x*blockDim.x + threadIdx.x; i < n; i += gridDim.x*blockDim.x)
        g_h[i] = 0.0f;
}

// shared tile loader: one halo pixel per thread, vector LDG, scalar STS
__device__ __forceinline__ void load_tile(float* sIn, const float* __restrict__ xp,
                                          const float* __restrict__ hp,
                                          int ty0, int tx0, int tid)
{
    if (tid < NHALO) {
        int sy = tid / SWID, sx = tid - sy*SWID;
        int gy = ty0 + sy - 1, gx = tx0 + sx - 1;
        float* dst = sIn + tid * CAP;
        if (gy >= 0 && gy < HH && gx >= 0 && gx < WW) {
            const float2* x2 = (const float2*)(xp + (gy*WW + gx)*CIN);
            float2 a = x2[0], b = x2[1], c = x2[2];
            dst[0]=a.x; dst[1]=a.y; dst[2]=b.x; dst[3]=b.y; dst[4]=c.x; dst[5]=c.y;
            const float4* h4 = (const float4*)(hp + (gy*WW + gx)*FF);
            #pragma unroll
            for (int j = 0; j < 8; ++j) {
                float4 v = h4[j];
                dst[6+4*j]=v.x; dst[7+4*j]=v.y; dst[8+4*j]=v.z; dst[9+4*j]=v.w;
            }
            dst[38] = 0.0f; dst[39] = 0.0f;     // channel padding
        } else {
            #pragma unroll
            for (int i = 0; i < CA_P; ++i) dst[i] = 0.0f;
        }
    }
}

// ---- Kernel A: gates. conv([x_t, h], W_A) -> z, r ; writes g_z, g_rh ----
// 4 warp-pure f-groups of 16 channels; each thread: 2 pixels; LDS.128 input fetch.
__global__ void __launch_bounds__(NTHREADS, 1)
stepA(const float* __restrict__ x, int s)
{
    extern __shared__ float sm[];
    float* sIn = sm;                 // NHALO*CAP
    float* sW  = sm + SIN_ELEMS;     // 9*CA_P*FA

    const int dir  = blockIdx.z;
    const int b    = blockIdx.y;
    const int tile = blockIdx.x;
    const int ty0  = (tile / TILESX) * TY;
    const int tx0  = (tile % TILESX) * TX;
    const int t    = dir ? (TT - 1 - s) : s;
    const int tid  = threadIdx.x;

    {
        const float4* src = (const float4*)(g_wA + dir*WA_ELEMS);
        float4* dst = (float4*)sW;
        for (int i = tid; i < WA_ELEMS/4; i += NTHREADS) dst[i] = src[i];
    }
    load_tile(sIn,
              x   + (size_t)((b*TT + t)*HH*WW)*CIN,
              g_h + (size_t)((dir*NBATCH + b)*HH*WW)*FF,
              ty0, tx0, tid);
    __syncthreads();

    const int g   = tid / PAIRS;          // f-group 0..3 (warp-pure: 160 = 5 warps)
    const int pid = tid - g*PAIRS;        // 0..159
    const int py  = pid / TX, px = pid - py*TX;   // py 0..7; second pixel at py+8

    unsigned long long acc0[8], acc1[8];
    {
        const unsigned long long* bb = (const unsigned long long*)(g_bA + dir*FA + g*16);
        #pragma unroll
        for (int j = 0; j < 8; ++j) { acc0[j] = bb[j]; acc1[j] = bb[j]; }
    }

    const float* ipb = sIn + (py*SWID + px)*CAP;
    const float* wgb = sW + g*16;
    #pragma unroll 1
    for (int k = 0; k < 9; ++k) {
        const int ky = k / 3, kx = k - ky*3;
        const float* ip0 = ipb + (ky*SWID + kx)*CAP;
        const float* ip1 = ip0 + 8*SWID*CAP;
        const float* wk  = wgb + k*(CA_P*FA);
        #pragma unroll
        for (int c4 = 0; c4 < CA_P/4; ++c4) {
            float4 a0 = *(const float4*)(ip0 + 4*c4);
            float4 a1 = *(const float4*)(ip1 + 4*c4);
            const float* wc = wk + 4*c4*FA;
            #pragma unroll
            for (int cc = 0; cc < 4; ++cc) {
                unsigned long long v0 = pack2(((const float*)&a0)[cc]);
                unsigned long long v1 = pack2(((const float*)&a1)[cc]);
                const ulonglong2* w2 = (const ulonglong2*)(wc + cc*FA);
                #pragma unroll
                for (int j = 0; j < 4; ++j) {
                    ulonglong2 w = w2[j];
                    ffma2(acc0[2*j],   v0, w.x);
                    ffma2(acc0[2*j+1], v0, w.y);
                    ffma2(acc1[2*j],   v1, w.x);
                    ffma2(acc1[2*j+1], v1, w.y);
                }
            }
        }
    }

    const int gx = tx0 + px;
    #pragma unroll
    for (int pp = 0; pp < 2; ++pp) {
        const int gy = ty0 + py + 8*pp;
        const unsigned long long* acc = pp ? acc1 : acc0;
        const int base = ((dir*NBATCH + b)*HH*WW + gy*WW + gx)*FF;
        if (g < 2) {   // z channels [16g, 16g+16)
            float4* zp = (float4*)(g_z + base + 16*g);
            #pragma unroll
            for (int j = 0; j < 4; ++j) {
                float a0,a1,a2,a3;
                unpack2(acc[2*j],   a0, a1);
                unpack2(acc[2*j+1], a2, a3);
                zp[j] = make_float4(sigm(a0), sigm(a1), sigm(a2), sigm(a3));
            }
        } else {       // r channels [16(g-2), ...)
            const int rf = 16*(g - 2);
            const float* hin = sIn + ((py + 8*pp + 1)*SWID + (px + 1))*CAP + CIN + rf;
            float4* rp = (float4*)(g_rh + base + rf);
            #pragma unroll
            for (int j = 0; j < 4; ++j) {
                float a0,a1,a2,a3;
                unpack2(acc[2*j],   a0, a1);
                unpack2(acc[2*j+1], a2, a3);
                rp[j] = make_float4(sigm(a0)*hin[4*j],   sigm(a1)*hin[4*j+1],
                                    sigm(a2)*hin[4*j+2], sigm(a3)*hin[4*j+3]);
            }
        }
    }
}

// ---- Kernel B: candidate + state update. conv([x_t, r*h], W_B) -> hh; h_new ----
// 4 warp-pure f-groups of 8 channels; each thread: 2 pixels; LDS.128 input fetch.
__global__ void __launch_bounds__(NTHREADS, 1)
stepB(const float* __restrict__ x, float* __restrict__ out, int s)
{
    extern __shared__ float sm[];
    float* sIn = sm;                 // NHALO*CAP
    float* sW  = sm + SIN_ELEMS;     // 9*CA_P*FB

    const int dir  = blockIdx.z;
    const int b    = blockIdx.y;
    const int tile = blockIdx.x;
    const int ty0  = (tile / TILESX) * TY;
    const int tx0  = (tile % TILESX) * TX;
    const int t    = dir ? (TT - 1 - s) : s;
    const int tid  = threadIdx.x;

    {
        const float4* src = (const float4*)(g_wB + dir*WB_ELEMS);
        float4* dst = (float4*)sW;
        for (int i = tid; i < WB_ELEMS/4; i += NTHREADS) dst[i] = src[i];
    }
    load_tile(sIn,
              x    + (size_t)((b*TT + t)*HH*WW)*CIN,
              g_rh + (size_t)((dir*NBATCH + b)*HH*WW)*FF,
              ty0, tx0, tid);
    __syncthreads();

    const int g   = tid / PAIRS;          // f-group 0..3, channels [8g, 8g+8)
    const int pid = tid - g*PAIRS;
    const int py  = pid / TX, px = pid - py*TX;

    unsigned long long acc0[4], acc1[4];
    {
        const unsigned long long* bb = (const unsigned long long*)(g_bB + dir*FB + g*8);
        #pragma unroll
        for (int j = 0; j < 4; ++j) { acc0[j] = bb[j]; acc1[j] = bb[j]; }
    }

    const float* ipb = sIn + (py*SWID + px)*CAP;
    const float* wgb = sW + g*8;
    #pragma unroll 1
    for (int k = 0; k < 9; ++k) {
        const int ky = k / 3, kx = k - ky*3;
        const float* ip0 = ipb + (ky*SWID + kx)*CAP;
        const float* ip1 = ip0 + 8*SWID*CAP;
        const float* wk  = wgb + k*(CA_P*FB);
        #pragma unroll
        for (int c4 = 0; c4 < CA_P/4; ++c4) {
            float4 a0 = *(const float4*)(ip0 + 4*c4);
            float4 a1 = *(const float4*)(ip1 + 4*c4);
            const float* wc = wk + 4*c4*FB;
            #pragma unroll
            for (int cc = 0; cc < 4; ++cc) {
                unsigned long long v0 = pack2(((const float*)&a0)[cc]);
                unsigned long long v1 = pack2(((const float*)&a1)[cc]);
                const ulonglong2* w2 = (const ulonglong2*)(wc + cc*FB);
                #pragma unroll
                for (int j = 0; j < 2; ++j) {
                    ulonglong2 w = w2[j];
                    ffma2(acc0[2*j],   v0, w.x);
                    ffma2(acc0[2*j+1], v0, w.y);
                    ffma2(acc1[2*j],   v1, w.x);
                    ffma2(acc1[2*j+1], v1, w.y);
                }
            }
        }
    }

    const int gx = tx0 + px;
    #pragma unroll
    for (int pp = 0; pp < 2; ++pp) {
        const int gy = ty0 + py + 8*pp;
        const unsigned long long* acc = pp ? acc1 : acc0;
        const int base  = ((dir*NBATCH + b)*HH*WW + gy*WW + gx)*FF + 8*g;
        const int obase = (((b*TT + t)*HH + gy)*WW + gx)*(2*FF) + dir*FF + 8*g;
        const float4* zp = (const float4*)(g_z + base);
        const float4* hp = (const float4*)(g_h + base);
        float4* hw = (float4*)(g_h + base);
        float4* ow = (float4*)(out + obase);
        #pragma unroll
        for (int j = 0; j < 2; ++j) {
            float p0,p1,p2,p3;
            unpack2(acc[2*j],   p0, p1);
            unpack2(acc[2*j+1], p2, p3);
            float4 z = zp[j];
            float4 h = hp[j];
            float4 hn;
            hn.x = z.x*h.x + (1.0f - z.x)*ftanh(p0);
            hn.y = z.y*h.y + (1.0f - z.y)*ftanh(p1);
            hn.z = z.z*h.z + (1.0f - z.z)*ftanh(p2);
            hn.w = z.w*h.w + (1.0f - z.w)*ftanh(p3);
            hw[j] = hn;
            ow[j] = hn;
        }
    }
}

extern "C" void kernel_launch(void* const* d_in, const int* in_sizes, int n_in,
                              void* d_out, int out_size)
{
    const float* x    = (const float*)d_in[0];
    const float* WxF  = (const float*)d_in[1];
    const float* bF   = (const float*)d_in[2];
    const float* WzrF = (const float*)d_in[3];
    const float* WhF  = (const float*)d_in[4];
    const float* WxB  = (const float*)d_in[5];
    const float* bB   = (const float*)d_in[6];
    const float* WzrB = (const float*)d_in[7];
    const float* WhB  = (const float*)d_in[8];
    float* out = (float*)d_out;

    const int smemA = (SIN_ELEMS + WA_ELEMS) * 4;   // ~158 KB
    const int smemB = (SIN_ELEMS + WB_ELEMS) * 4;   // ~113 KB
    cudaFuncSetAttribute(stepA, cudaFuncAttributeMaxDynamicSharedMemorySize, smemA);
    cudaFuncSetAttribute(stepB, cudaFuncAttributeMaxDynamicSharedMemorySize, smemB);

    pack_kernel<<<64, 256>>>(WxF, bF, WzrF, WhF, WxB, bB, WzrB, WhB);
    zero_h_kernel<<<256, 256>>>();

    dim3 grid(TILESY * TILESX, NBATCH, 2);   // 30 tiles x 2 batch x 2 dir = 120 blocks
    for (int s = 0; s < TT; ++s) {
        stepA<<<grid, NTHREADS, smemA>>>(x, s);
        stepB<<<grid, NTHREADS, smemB>>>(x, out, s);
    }
}